// round 15
// baseline (speedup 1.0000x reference)
#include <cuda_runtime.h>
#include <cuda_bf16.h>
#include <math.h>

// Shapes fixed for this bench: B=4, H=8, N=512, DK=64
#define BB 4
#define HH 8
#define NN 512
#define DKK 64
#define TI 8                 // i-rows per CTA
#define NT 512               // threads per CTA (16 warps)
#define SCALE 0.125f         // 1/sqrt(64)
#define SROW 516             // padded score row (stride mod 32 = 4)
#define TIBLK (HH*SROW + 4)  // 4132 (stride mod 32 = 4)

// smem layout in floats
#define S_OFF    0
#define RED1_OFF (TI*TIBLK)                    // 33056 ; [2][TI*HH][DKK] p.v
#define RED2_OFF (RED1_OFF + 2*TI*HH*DKK)      // 41248 ; [2][TI*HH][DKK] p.rel
#define LP_OFF   (RED2_OFF + 2*TI*HH*DKK)      // 49440 ; [2][TI*HH] row sums
#define SMEM_FLOATS (LP_OFF + 2*TI*HH)         // 49568
#define SMEM_BYTES (SMEM_FLOATS * 4)           // 198272 (< 227 KB)

// ---------------- packed f32x2 helpers (FFMA2 on sm_103a) ----------------
__device__ __forceinline__ unsigned long long f2u(float2 a) {
    unsigned long long r;
    asm("mov.b64 %0, {%1, %2};" : "=l"(r) : "f"(a.x), "f"(a.y));
    return r;
}
__device__ __forceinline__ float2 u2f(unsigned long long a) {
    float2 r;
    asm("mov.b64 {%0, %1}, %2;" : "=f"(r.x), "=f"(r.y) : "l"(a));
    return r;
}
__device__ __forceinline__ float2 ffma2(float2 a, float2 b, float2 c) {
    unsigned long long r;
    asm("fma.rn.f32x2 %0, %1, %2, %3;"
        : "=l"(r) : "l"(f2u(a)), "l"(f2u(b)), "l"(f2u(c)));
    return u2f(r);
}
__device__ __forceinline__ float2 lo2(float4 v) { return make_float2(v.x, v.y); }
__device__ __forceinline__ float2 hi2(float4 v) { return make_float2(v.z, v.w); }

// Reduce 8 per-lane values r[0..7] across the 8 dd-lanes; lane dd -> sum of r[dd].
__device__ __forceinline__ float butterfly8(const float r[8],
                                            bool b0, bool b1, bool b2) {
    float c0 = b2 ? r[4] : r[0];
    float c1 = b2 ? r[5] : r[1];
    float c2 = b2 ? r[6] : r[2];
    float c3 = b2 ? r[7] : r[3];
    float d0 = b2 ? r[0] : r[4];
    float d1 = b2 ? r[1] : r[5];
    float d2 = b2 ? r[2] : r[6];
    float d3 = b2 ? r[3] : r[7];
    c0 += __shfl_xor_sync(0xffffffffu, d0, 4);
    c1 += __shfl_xor_sync(0xffffffffu, d1, 4);
    c2 += __shfl_xor_sync(0xffffffffu, d2, 4);
    c3 += __shfl_xor_sync(0xffffffffu, d3, 4);
    float e0 = b1 ? c2 : c0;
    float e1 = b1 ? c3 : c1;
    float f0 = b1 ? c0 : c2;
    float f1 = b1 ? c1 : c3;
    e0 += __shfl_xor_sync(0xffffffffu, f0, 2);
    e1 += __shfl_xor_sync(0xffffffffu, f1, 2);
    float w = b0 ? e1 : e0;
    float o = b0 ? e0 : e1;
    w += __shfl_xor_sync(0xffffffffu, o, 1);
    return w;
}

// TWO interleaved butterfly8 reductions (independent shfl chains overlap).
// Returns (w_r, w_s): lane dd gets full sums of r[dd] and s[dd].
__device__ __forceinline__ float2 butterfly8x2(const float r[8], const float s[8],
                                               bool b0, bool b1, bool b2) {
    float rc0 = b2 ? r[4] : r[0];
    float rc1 = b2 ? r[5] : r[1];
    float rc2 = b2 ? r[6] : r[2];
    float rc3 = b2 ? r[7] : r[3];
    float rd0 = b2 ? r[0] : r[4];
    float rd1 = b2 ? r[1] : r[5];
    float rd2 = b2 ? r[2] : r[6];
    float rd3 = b2 ? r[3] : r[7];
    float sc0 = b2 ? s[4] : s[0];
    float sc1 = b2 ? s[5] : s[1];
    float sc2 = b2 ? s[6] : s[2];
    float sc3 = b2 ? s[7] : s[3];
    float sd0 = b2 ? s[0] : s[4];
    float sd1 = b2 ? s[1] : s[5];
    float sd2 = b2 ? s[2] : s[6];
    float sd3 = b2 ? s[3] : s[7];
    rc0 += __shfl_xor_sync(0xffffffffu, rd0, 4);
    sc0 += __shfl_xor_sync(0xffffffffu, sd0, 4);
    rc1 += __shfl_xor_sync(0xffffffffu, rd1, 4);
    sc1 += __shfl_xor_sync(0xffffffffu, sd1, 4);
    rc2 += __shfl_xor_sync(0xffffffffu, rd2, 4);
    sc2 += __shfl_xor_sync(0xffffffffu, sd2, 4);
    rc3 += __shfl_xor_sync(0xffffffffu, rd3, 4);
    sc3 += __shfl_xor_sync(0xffffffffu, sd3, 4);
    float re0 = b1 ? rc2 : rc0;
    float re1 = b1 ? rc3 : rc1;
    float rf0 = b1 ? rc0 : rc2;
    float rf1 = b1 ? rc1 : rc3;
    float se0 = b1 ? sc2 : sc0;
    float se1 = b1 ? sc3 : sc1;
    float sf0 = b1 ? sc0 : sc2;
    float sf1 = b1 ? sc1 : sc3;
    re0 += __shfl_xor_sync(0xffffffffu, rf0, 2);
    se0 += __shfl_xor_sync(0xffffffffu, sf0, 2);
    re1 += __shfl_xor_sync(0xffffffffu, rf1, 2);
    se1 += __shfl_xor_sync(0xffffffffu, sf1, 2);
    float wr = b0 ? re1 : re0;
    float orr = b0 ? re0 : re1;
    float ws = b0 ? se1 : se0;
    float oss = b0 ? se0 : se1;
    wr += __shfl_xor_sync(0xffffffffu, orr, 1);
    ws += __shfl_xor_sync(0xffffffffu, oss, 1);
    return make_float2(wr, ws);
}

__global__ __launch_bounds__(NT, 1)
void rel_attn_kernel(const float* __restrict__ q,
                     const float* __restrict__ k,
                     const float* __restrict__ v,
                     const float* __restrict__ rel,
                     const float* __restrict__ mask,
                     float* __restrict__ out) {
    extern __shared__ float sm[];
    float* s_s   = sm + S_OFF;     // [TI]{[HH][SROW]} scores(+mask) -> e
    float* red1  = sm + RED1_OFF;  // [2][TI*HH][DKK] p.v per-jhalf partials
    float* red2  = sm + RED2_OFF;  // [2][TI*HH][DKK] p.rel per-jhalf partials
    float* lpart = sm + LP_OFF;    // [2][TI*HH] row-sum partials

    const int bid  = blockIdx.x;
    const int b    = bid >> 6;
    const int i0   = (bid & 63) * TI;
    const int tid  = threadIdx.x;
    const int warp = tid >> 5;
    const int lane = tid & 31;
    const int dd   = lane & 7;
    const int jj   = lane >> 3;
    const bool b0  = (dd & 1) != 0;
    const bool b1  = (dd & 2) != 0;
    const bool b2  = (dd & 4) != 0;

    const int sub  = warp & 7;           // head (1a/2a) or ti (1b/2b)
    const int jh   = warp >> 3;          // j-half owned by this warp
    const int jo   = jh * (NN / 2);

    const float2 z2 = make_float2(0.f, 0.f);

    // ===== Phase 1a: s = (scale*q).k + mask ; warp=(h, jhalf) ===============
    // Two j-groups per iteration -> two interleaved butterfly chains.
    {
        const int h = sub;
        float4 qa[TI], qb[TI];
#pragma unroll
        for (int ti = 0; ti < TI; ti++) {
            const float* qp = q + ((size_t)(b * HH + h) * NN + (i0 + ti)) * DKK + dd * 8;
            float4 a = *(const float4*)qp;
            float4 c = *(const float4*)(qp + 4);
            a.x *= SCALE; a.y *= SCALE; a.z *= SCALE; a.w *= SCALE;
            c.x *= SCALE; c.y *= SCALE; c.z *= SCALE; c.w *= SCALE;
            qa[ti] = a; qb[ti] = c;
        }
        const float* kbase = k + ((size_t)(b * HH + h) * NN) * DKK + dd * 8;
#pragma unroll 2
        for (int s = 0; s < NN / 16; s++) {
            const int ja = jo + s * 8 + jj;
            const int jb = ja + 4;
            const float4 ka0 = *(const float4*)(kbase + (size_t)ja * DKK);
            const float4 kb0 = *(const float4*)(kbase + (size_t)ja * DKK + 4);
            const float4 ka1 = *(const float4*)(kbase + (size_t)jb * DKK);
            const float4 kb1 = *(const float4*)(kbase + (size_t)jb * DKK + 4);
            float r0[TI], r1[TI];
#pragma unroll
            for (int ti = 0; ti < TI; ti++) {
                float2 a = ffma2(lo2(qa[ti]), lo2(ka0), z2);
                a = ffma2(hi2(qa[ti]), hi2(ka0), a);
                a = ffma2(lo2(qb[ti]), lo2(kb0), a);
                a = ffma2(hi2(qb[ti]), hi2(kb0), a);
                r0[ti] = a.x + a.y;
                float2 c = ffma2(lo2(qa[ti]), lo2(ka1), z2);
                c = ffma2(hi2(qa[ti]), hi2(ka1), c);
                c = ffma2(lo2(qb[ti]), lo2(kb1), c);
                c = ffma2(hi2(qb[ti]), hi2(kb1), c);
                r1[ti] = c.x + c.y;
            }
            const float2 w = butterfly8x2(r0, r1, b0, b1, b2); // lane dd -> ti=dd
            s_s[dd * TIBLK + h * SROW + ja] = w.x;             // conflict-free
            s_s[dd * TIBLK + h * SROW + jb] = w.y;
        }

        // --- mask epilogue: s_s rows (all ti, h, j in jhalf) += mask --------
#pragma unroll
        for (int ti = 0; ti < TI; ti++) {
            const float4* mp4 = (const float4*)(mask +
                ((size_t)(b * HH + h) * NN + (i0 + ti)) * NN + jo);
            float4* sr4 = (float4*)(s_s + ti * TIBLK + h * SROW + jo);
#pragma unroll
            for (int t = 0; t < 2; t++) {
                const int x = t * 32 + lane;             // 64 float4 per row-half
                float4 sv = sr4[x];
                const float4 mv = mp4[x];
                sv.x += mv.x; sv.y += mv.y; sv.z += mv.z; sv.w += mv.w;
                sr4[x] = sv;
            }
        }
    }
    __syncthreads();

    // ===== Phase 1b: e = exp(q.rel + s_s) ; warp=(ti, jhalf), dual-j ========
    {
        const int ti = sub;
        float4 qa[HH], qb[HH];
#pragma unroll
        for (int h = 0; h < HH; h++) {
            const float* qp = q + ((size_t)(b * HH + h) * NN + (i0 + ti)) * DKK + dd * 8;
            qa[h] = *(const float4*)qp;
            qb[h] = *(const float4*)(qp + 4);
        }
        const float* rbase = rel + (((size_t)b * NN + (i0 + ti)) * NN) * DKK + dd * 8;
        float* srow = s_s + ti * TIBLK + dd * SROW;
        float lsum = 0.f;

#pragma unroll 2
        for (int s = 0; s < NN / 16; s++) {
            const int ja = jo + s * 8 + jj;
            const int jb = ja + 4;
            const float4 ra0 = __ldg((const float4*)(rbase + (size_t)ja * DKK));
            const float4 rb0 = __ldg((const float4*)(rbase + (size_t)ja * DKK + 4));
            const float4 ra1 = __ldg((const float4*)(rbase + (size_t)jb * DKK));
            const float4 rb1 = __ldg((const float4*)(rbase + (size_t)jb * DKK + 4));
            float r0[HH], r1[HH];
#pragma unroll
            for (int h = 0; h < HH; h++) {
                float2 a = ffma2(lo2(qa[h]), lo2(ra0), z2);
                a = ffma2(hi2(qa[h]), hi2(ra0), a);
                a = ffma2(lo2(qb[h]), lo2(rb0), a);
                a = ffma2(hi2(qb[h]), hi2(rb0), a);
                r0[h] = a.x + a.y;
                float2 c = ffma2(lo2(qa[h]), lo2(ra1), z2);
                c = ffma2(hi2(qa[h]), hi2(ra1), c);
                c = ffma2(lo2(qb[h]), lo2(rb1), c);
                c = ffma2(hi2(qb[h]), hi2(rb1), c);
                r1[h] = c.x + c.y;
            }
            const float2 w = butterfly8x2(r0, r1, b0, b1, b2); // lane dd -> h=dd
            const float e0 = __expf(w.x + srow[ja]);           // content+mask in s_s
            const float e1 = __expf(w.y + srow[jb]);
            srow[ja] = e0;                                     // conflict-free RMW
            srow[jb] = e1;
            lsum += e0 + e1;
        }
        // row-sum partial: reduce over the 4 jj lanes for fixed dd
        lsum += __shfl_xor_sync(0xffffffffu, lsum, 8);
        lsum += __shfl_xor_sync(0xffffffffu, lsum, 16);
        if (jj == 0) lpart[jh * (TI * HH) + ti * HH + dd] = lsum;
    }
    __syncthreads();

    // ===== Phases 2a / 2b (order alternates by CTA parity) ==================
    auto phase2b = [&]() {   // out2 = p.rel ; warp=(ti, jhalf), j DESCENDING
        const int ti = sub;
        float2 acc[HH][4];
#pragma unroll
        for (int h = 0; h < HH; h++)
#pragma unroll
            for (int c = 0; c < 4; c++) acc[h][c] = z2;

        const float* rbase = rel + (((size_t)b * NN + (i0 + ti)) * NN) * DKK + dd * 8;
        const int jstart = jo + (NN / 8 - 1) * 4 + jj;
        float4 ra = __ldcs((const float4*)(rbase + (size_t)jstart * DKK));
        float4 rb = __ldcs((const float4*)(rbase + (size_t)jstart * DKK + 4));
#pragma unroll 2
        for (int s = NN / 8 - 1; s >= 0; s--) {
            const int j  = jo + s * 4 + jj;
            const int sn = (s > 0) ? s - 1 : 0;
            const int jn = jo + sn * 4 + jj;
            const float4 na = __ldcs((const float4*)(rbase + (size_t)jn * DKK));
            const float4 nb = __ldcs((const float4*)(rbase + (size_t)jn * DKK + 4));
#pragma unroll
            for (int h = 0; h < HH; h++) {
                const float e = s_s[ti * TIBLK + h * SROW + j];
                const float2 e2 = make_float2(e, e);
                acc[h][0] = ffma2(e2, lo2(ra), acc[h][0]);
                acc[h][1] = ffma2(e2, hi2(ra), acc[h][1]);
                acc[h][2] = ffma2(e2, lo2(rb), acc[h][2]);
                acc[h][3] = ffma2(e2, hi2(rb), acc[h][3]);
            }
            ra = na; rb = nb;
        }
#pragma unroll
        for (int h = 0; h < HH; h++)
#pragma unroll
            for (int c = 0; c < 4; c++) {
                acc[h][c].x += __shfl_xor_sync(0xffffffffu, acc[h][c].x, 8);
                acc[h][c].x += __shfl_xor_sync(0xffffffffu, acc[h][c].x, 16);
                acc[h][c].y += __shfl_xor_sync(0xffffffffu, acc[h][c].y, 8);
                acc[h][c].y += __shfl_xor_sync(0xffffffffu, acc[h][c].y, 16);
            }
        if (jj == 0) {
#pragma unroll
            for (int h = 0; h < HH; h++) {
                float* rp = red2 + ((size_t)jh * TI * HH * DKK) +
                            (ti * HH + h) * DKK + dd * 8;
                *(float4*)rp       = make_float4(acc[h][0].x, acc[h][0].y,
                                                 acc[h][1].x, acc[h][1].y);
                *(float4*)(rp + 4) = make_float4(acc[h][2].x, acc[h][2].y,
                                                 acc[h][3].x, acc[h][3].y);
            }
        }
    };

    auto phase2a = [&]() {   // out1 = p.v ; warp=(h, jhalf)
        const int h = sub;
        float2 acc[TI][4];
#pragma unroll
        for (int ti = 0; ti < TI; ti++)
#pragma unroll
            for (int c = 0; c < 4; c++) acc[ti][c] = z2;

        const float* vbase = v + ((size_t)(b * HH + h) * NN) * DKK + dd * 8;
        float4 va = *(const float4*)(vbase + (size_t)(jo + jj) * DKK);
        float4 vb = *(const float4*)(vbase + (size_t)(jo + jj) * DKK + 4);
#pragma unroll 2
        for (int s = 0; s < NN / 8; s++) {
            const int j  = jo + s * 4 + jj;
            const int sn = (s < NN / 8 - 1) ? s + 1 : s;
            const int jn = jo + sn * 4 + jj;
            const float4 na = *(const float4*)(vbase + (size_t)jn * DKK);
            const float4 nb = *(const float4*)(vbase + (size_t)jn * DKK + 4);
#pragma unroll
            for (int ti = 0; ti < TI; ti++) {
                const float e = s_s[ti * TIBLK + h * SROW + j];
                const float2 e2 = make_float2(e, e);
                acc[ti][0] = ffma2(e2, lo2(va), acc[ti][0]);
                acc[ti][1] = ffma2(e2, hi2(va), acc[ti][1]);
                acc[ti][2] = ffma2(e2, lo2(vb), acc[ti][2]);
                acc[ti][3] = ffma2(e2, hi2(vb), acc[ti][3]);
            }
            va = na; vb = nb;
        }
#pragma unroll
        for (int ti = 0; ti < TI; ti++)
#pragma unroll
            for (int c = 0; c < 4; c++) {
                acc[ti][c].x += __shfl_xor_sync(0xffffffffu, acc[ti][c].x, 8);
                acc[ti][c].x += __shfl_xor_sync(0xffffffffu, acc[ti][c].x, 16);
                acc[ti][c].y += __shfl_xor_sync(0xffffffffu, acc[ti][c].y, 8);
                acc[ti][c].y += __shfl_xor_sync(0xffffffffu, acc[ti][c].y, 16);
            }
        if (jj == 0) {
#pragma unroll
            for (int ti = 0; ti < TI; ti++) {
                float* rp = red1 + ((size_t)jh * TI * HH * DKK) +
                            (ti * HH + h) * DKK + dd * 8;
                *(float4*)rp       = make_float4(acc[ti][0].x, acc[ti][0].y,
                                                 acc[ti][1].x, acc[ti][1].y);
                *(float4*)(rp + 4) = make_float4(acc[ti][2].x, acc[ti][2].y,
                                                 acc[ti][3].x, acc[ti][3].y);
            }
        }
    };

    if ((bid & 1) == 0) { phase2b(); phase2a(); }
    else                { phase2a(); phase2b(); }
    __syncthreads();

    // ===== Combine + normalize + store (float4) =============================
    {
        const int Q = TI * HH * DKK / 4;            // 1024 float4s
        const float4* r14 = (const float4*)red1;
        const float4* r24 = (const float4*)red2;
#pragma unroll
        for (int it = 0; it < 2; it++) {
            const int idx4 = it * NT + tid;
            const float4 a0 = r14[idx4];
            const float4 a1 = r14[Q + idx4];
            const float4 c0 = r24[idx4];
            const float4 c1 = r24[Q + idx4];
            const int row = idx4 >> 4;               // ti*8+h
            const int ti  = row >> 3;
            const int h   = row & 7;
            const int d   = (idx4 & 15) << 2;
            const float s = 1.0f / (lpart[row] + lpart[TI * HH + row]);
            float4 o;
            o.x = ((a0.x + a1.x) + (c0.x + c1.x)) * s;
            o.y = ((a0.y + a1.y) + (c0.y + c1.y)) * s;
            o.z = ((a0.z + a1.z) + (c0.z + c1.z)) * s;
            o.w = ((a0.w + a1.w) + (c0.w + c1.w)) * s;
            *(float4*)&out[((size_t)(b * HH + h) * NN + (i0 + ti)) * DKK + d] = o;
        }
    }
}

extern "C" void kernel_launch(void* const* d_in, const int* in_sizes, int n_in,
                              void* d_out, int out_size) {
    const float* q    = (const float*)d_in[0];
    const float* k    = (const float*)d_in[1];
    const float* v    = (const float*)d_in[2];
    const float* rel  = (const float*)d_in[3];
    const float* mask = (const float*)d_in[4];
    float* out = (float*)d_out;

    cudaFuncSetAttribute(rel_attn_kernel,
                         cudaFuncAttributeMaxDynamicSharedMemorySize, SMEM_BYTES);
    rel_attn_kernel<<<BB * (NN / TI), NT, SMEM_BYTES>>>(q, k, v, rel, mask, out);
}

// round 16
// speedup vs baseline: 1.0258x; 1.0258x over previous
#include <cuda_runtime.h>
#include <cuda_bf16.h>
#include <math.h>

// Shapes fixed for this bench: B=4, H=8, N=512, DK=64
#define BB 4
#define HH 8
#define NN 512
#define DKK 64
#define TI 8                 // i-rows per CTA
#define NT 512               // threads per CTA (16 warps)
#define SCALE 0.125f         // 1/sqrt(64)
#define SROW 516             // padded score row (stride mod 32 = 4)
#define TIBLK (HH*SROW + 4)  // 4132 (stride mod 32 = 4)

// smem layout in floats
#define S_OFF    0
#define RED1_OFF (TI*TIBLK)                    // 33056 ; [2][TI*HH][DKK] p.v
#define RED2_OFF (RED1_OFF + 2*TI*HH*DKK)      // 41248 ; [2][TI*HH][DKK] p.rel
#define LP_OFF   (RED2_OFF + 2*TI*HH*DKK)      // 49440 ; [2][TI*HH] row sums
#define SMEM_FLOATS (LP_OFF + 2*TI*HH)         // 49568
#define SMEM_BYTES (SMEM_FLOATS * 4)           // 198272 (< 227 KB)

// ---------------- packed f32x2 helpers (FFMA2 on sm_103a) ----------------
__device__ __forceinline__ unsigned long long f2u(float2 a) {
    unsigned long long r;
    asm("mov.b64 %0, {%1, %2};" : "=l"(r) : "f"(a.x), "f"(a.y));
    return r;
}
__device__ __forceinline__ float2 u2f(unsigned long long a) {
    float2 r;
    asm("mov.b64 {%0, %1}, %2;" : "=f"(r.x), "=f"(r.y) : "l"(a));
    return r;
}
__device__ __forceinline__ float2 ffma2(float2 a, float2 b, float2 c) {
    unsigned long long r;
    asm("fma.rn.f32x2 %0, %1, %2, %3;"
        : "=l"(r) : "l"(f2u(a)), "l"(f2u(b)), "l"(f2u(c)));
    return u2f(r);
}
__device__ __forceinline__ float2 lo2(float4 v) { return make_float2(v.x, v.y); }
__device__ __forceinline__ float2 hi2(float4 v) { return make_float2(v.z, v.w); }

// Reduce 8 per-lane values r[0..7] across the 8 dd-lanes; lane dd -> sum of r[dd].
__device__ __forceinline__ float butterfly8(const float r[8],
                                            bool b0, bool b1, bool b2) {
    float c0 = b2 ? r[4] : r[0];
    float c1 = b2 ? r[5] : r[1];
    float c2 = b2 ? r[6] : r[2];
    float c3 = b2 ? r[7] : r[3];
    float d0 = b2 ? r[0] : r[4];
    float d1 = b2 ? r[1] : r[5];
    float d2 = b2 ? r[2] : r[6];
    float d3 = b2 ? r[3] : r[7];
    c0 += __shfl_xor_sync(0xffffffffu, d0, 4);
    c1 += __shfl_xor_sync(0xffffffffu, d1, 4);
    c2 += __shfl_xor_sync(0xffffffffu, d2, 4);
    c3 += __shfl_xor_sync(0xffffffffu, d3, 4);
    float e0 = b1 ? c2 : c0;
    float e1 = b1 ? c3 : c1;
    float f0 = b1 ? c0 : c2;
    float f1 = b1 ? c1 : c3;
    e0 += __shfl_xor_sync(0xffffffffu, f0, 2);
    e1 += __shfl_xor_sync(0xffffffffu, f1, 2);
    float w = b0 ? e1 : e0;
    float o = b0 ? e0 : e1;
    w += __shfl_xor_sync(0xffffffffu, o, 1);
    return w;
}

__global__ __launch_bounds__(NT, 1)
void rel_attn_kernel(const float* __restrict__ q,
                     const float* __restrict__ k,
                     const float* __restrict__ v,
                     const float* __restrict__ rel,
                     const float* __restrict__ mask,
                     float* __restrict__ out) {
    extern __shared__ float sm[];
    float* s_s   = sm + S_OFF;     // [TI]{[HH][SROW]} scores(+mask) -> e
    float* red1  = sm + RED1_OFF;  // [2][TI*HH][DKK] p.v per-jhalf partials
    float* red2  = sm + RED2_OFF;  // [2][TI*HH][DKK] p.rel per-jhalf partials
    float* lpart = sm + LP_OFF;    // [2][TI*HH] row-sum partials

    const int bid  = blockIdx.x;
    const int b    = bid >> 6;
    const int i0   = (bid & 63) * TI;
    const int tid  = threadIdx.x;
    const int warp = tid >> 5;
    const int lane = tid & 31;
    const int dd   = lane & 7;
    const int jj   = lane >> 3;
    const bool b0  = (dd & 1) != 0;
    const bool b1  = (dd & 2) != 0;
    const bool b2  = (dd & 4) != 0;

    const int sub  = warp & 7;           // head (1a/2a) or ti (1b/2b)
    const int jh   = warp >> 3;          // j-half owned by this warp
    const int jo   = jh * (NN / 2);

    const float2 z2 = make_float2(0.f, 0.f);

    // ===== Phase 1a: s = (scale*q).k + mask ; warp=(h, jhalf) ===============
    {
        const int h = sub;
        float4 qa[TI], qb[TI];
#pragma unroll
        for (int ti = 0; ti < TI; ti++) {
            const float* qp = q + ((size_t)(b * HH + h) * NN + (i0 + ti)) * DKK + dd * 8;
            float4 a = *(const float4*)qp;
            float4 c = *(const float4*)(qp + 4);
            a.x *= SCALE; a.y *= SCALE; a.z *= SCALE; a.w *= SCALE;
            c.x *= SCALE; c.y *= SCALE; c.z *= SCALE; c.w *= SCALE;
            qa[ti] = a; qb[ti] = c;
        }
        const float* kbase = k + ((size_t)(b * HH + h) * NN) * DKK + dd * 8;
        float4 ka = *(const float4*)(kbase + (size_t)(jo + jj) * DKK);
        float4 kb = *(const float4*)(kbase + (size_t)(jo + jj) * DKK + 4);
#pragma unroll 2
        for (int s = 0; s < NN / 8; s++) {
            const int j  = jo + s * 4 + jj;
            const int sn = (s < NN / 8 - 1) ? s + 1 : s;
            const int jn = jo + sn * 4 + jj;
            const float4 na = *(const float4*)(kbase + (size_t)jn * DKK);
            const float4 nb = *(const float4*)(kbase + (size_t)jn * DKK + 4);
            float r[TI];
#pragma unroll
            for (int ti = 0; ti < TI; ti++) {
                float2 a = ffma2(lo2(qa[ti]), lo2(ka), z2);
                a = ffma2(hi2(qa[ti]), hi2(ka), a);
                a = ffma2(lo2(qb[ti]), lo2(kb), a);
                a = ffma2(hi2(qb[ti]), hi2(kb), a);
                r[ti] = a.x + a.y;
            }
            const float w = butterfly8(r, b0, b1, b2);   // lane dd -> ti=dd
            s_s[dd * TIBLK + h * SROW + j] = w;          // conflict-free
            ka = na; kb = nb;
        }

        // --- mask epilogue: s_s rows (all ti, h, j in jhalf) += mask --------
#pragma unroll
        for (int ti = 0; ti < TI; ti++) {
            const float4* mp4 = (const float4*)(mask +
                ((size_t)(b * HH + h) * NN + (i0 + ti)) * NN + jo);
            float4* sr4 = (float4*)(s_s + ti * TIBLK + h * SROW + jo);
#pragma unroll
            for (int t = 0; t < 2; t++) {
                const int x = t * 32 + lane;             // 64 float4 per row-half
                float4 sv = sr4[x];
                const float4 mv = mp4[x];
                sv.x += mv.x; sv.y += mv.y; sv.z += mv.z; sv.w += mv.w;
                sr4[x] = sv;
            }
        }
    }
    __syncthreads();

    // ===== Phase 1b: e = exp(q.rel + s_s) ; warp=(ti, jhalf), PF2 ==========
    {
        const int ti = sub;
        float4 qa[HH], qb[HH];
#pragma unroll
        for (int h = 0; h < HH; h++) {
            const float* qp = q + ((size_t)(b * HH + h) * NN + (i0 + ti)) * DKK + dd * 8;
            qa[h] = *(const float4*)qp;
            qb[h] = *(const float4*)(qp + 4);
        }
        const float* rbase = rel + (((size_t)b * NN + (i0 + ti)) * NN) * DKK + dd * 8;
        float* srow = s_s + ti * TIBLK + dd * SROW;
        float lsum = 0.f;

        // prefetch ring, distance 2
        float4 pa[2], pb[2];
        pa[0] = __ldg((const float4*)(rbase + (size_t)(jo + jj) * DKK));
        pb[0] = __ldg((const float4*)(rbase + (size_t)(jo + jj) * DKK + 4));
        pa[1] = __ldg((const float4*)(rbase + (size_t)(jo + 4 + jj) * DKK));
        pb[1] = __ldg((const float4*)(rbase + (size_t)(jo + 4 + jj) * DKK + 4));
#pragma unroll 2
        for (int s = 0; s < NN / 8; s++) {
            const int j   = jo + s * 4 + jj;
            const int cur = s & 1;
            const float4 ra = pa[cur];
            const float4 rb = pb[cur];
            const int sn = (s < NN / 8 - 2) ? s + 2 : s;
            const int jn = jo + sn * 4 + jj;
            pa[cur] = __ldg((const float4*)(rbase + (size_t)jn * DKK));
            pb[cur] = __ldg((const float4*)(rbase + (size_t)jn * DKK + 4));
            float r[HH];
#pragma unroll
            for (int h = 0; h < HH; h++) {
                float2 a = ffma2(lo2(qa[h]), lo2(ra), z2);
                a = ffma2(hi2(qa[h]), hi2(ra), a);
                a = ffma2(lo2(qb[h]), lo2(rb), a);
                a = ffma2(hi2(qb[h]), hi2(rb), a);
                r[h] = a.x + a.y;
            }
            const float w = butterfly8(r, b0, b1, b2);   // lane dd -> h=dd
            const float e = __expf(w + srow[j]);         // content+mask in s_s
            srow[j] = e;                                 // conflict-free RMW
            lsum += e;
        }
        // row-sum partial: reduce over the 4 jj lanes for fixed dd
        lsum += __shfl_xor_sync(0xffffffffu, lsum, 8);
        lsum += __shfl_xor_sync(0xffffffffu, lsum, 16);
        if (jj == 0) lpart[jh * (TI * HH) + ti * HH + dd] = lsum;
    }
    __syncthreads();

    // ===== Phases 2a / 2b (order alternates by CTA parity) ==================
    auto phase2b = [&]() {   // out2 = p.rel ; warp=(ti, jhalf), j DESCENDING, PF2
        const int ti = sub;
        float2 acc[HH][4];
#pragma unroll
        for (int h = 0; h < HH; h++)
#pragma unroll
            for (int c = 0; c < 4; c++) acc[h][c] = z2;

        const float* rbase = rel + (((size_t)b * NN + (i0 + ti)) * NN) * DKK + dd * 8;
        float4 pa[2], pb[2];
        {
            const int j1 = jo + (NN / 8 - 1) * 4 + jj;
            const int j2 = jo + (NN / 8 - 2) * 4 + jj;
            pa[1] = __ldcs((const float4*)(rbase + (size_t)j1 * DKK));
            pb[1] = __ldcs((const float4*)(rbase + (size_t)j1 * DKK + 4));
            pa[0] = __ldcs((const float4*)(rbase + (size_t)j2 * DKK));
            pb[0] = __ldcs((const float4*)(rbase + (size_t)j2 * DKK + 4));
        }
#pragma unroll 2
        for (int s = NN / 8 - 1; s >= 0; s--) {
            const int j   = jo + s * 4 + jj;
            const int cur = s & 1;
            const float4 ra = pa[cur];
            const float4 rb = pb[cur];
            const int sn = (s > 1) ? s - 2 : s;
            const int jn = jo + sn * 4 + jj;
            pa[cur] = __ldcs((const float4*)(rbase + (size_t)jn * DKK));
            pb[cur] = __ldcs((const float4*)(rbase + (size_t)jn * DKK + 4));
#pragma unroll
            for (int h = 0; h < HH; h++) {
                const float e = s_s[ti * TIBLK + h * SROW + j];
                const float2 e2 = make_float2(e, e);
                acc[h][0] = ffma2(e2, lo2(ra), acc[h][0]);
                acc[h][1] = ffma2(e2, hi2(ra), acc[h][1]);
                acc[h][2] = ffma2(e2, lo2(rb), acc[h][2]);
                acc[h][3] = ffma2(e2, hi2(rb), acc[h][3]);
            }
        }
#pragma unroll
        for (int h = 0; h < HH; h++)
#pragma unroll
            for (int c = 0; c < 4; c++) {
                acc[h][c].x += __shfl_xor_sync(0xffffffffu, acc[h][c].x, 8);
                acc[h][c].x += __shfl_xor_sync(0xffffffffu, acc[h][c].x, 16);
                acc[h][c].y += __shfl_xor_sync(0xffffffffu, acc[h][c].y, 8);
                acc[h][c].y += __shfl_xor_sync(0xffffffffu, acc[h][c].y, 16);
            }
        if (jj == 0) {
#pragma unroll
            for (int h = 0; h < HH; h++) {
                float* rp = red2 + ((size_t)jh * TI * HH * DKK) +
                            (ti * HH + h) * DKK + dd * 8;
                *(float4*)rp       = make_float4(acc[h][0].x, acc[h][0].y,
                                                 acc[h][1].x, acc[h][1].y);
                *(float4*)(rp + 4) = make_float4(acc[h][2].x, acc[h][2].y,
                                                 acc[h][3].x, acc[h][3].y);
            }
        }
    };

    auto phase2a = [&]() {   // out1 = p.v ; warp=(h, jhalf)
        const int h = sub;
        float2 acc[TI][4];
#pragma unroll
        for (int ti = 0; ti < TI; ti++)
#pragma unroll
            for (int c = 0; c < 4; c++) acc[ti][c] = z2;

        const float* vbase = v + ((size_t)(b * HH + h) * NN) * DKK + dd * 8;
        float4 va = *(const float4*)(vbase + (size_t)(jo + jj) * DKK);
        float4 vb = *(const float4*)(vbase + (size_t)(jo + jj) * DKK + 4);
#pragma unroll 2
        for (int s = 0; s < NN / 8; s++) {
            const int j  = jo + s * 4 + jj;
            const int sn = (s < NN / 8 - 1) ? s + 1 : s;
            const int jn = jo + sn * 4 + jj;
            const float4 na = *(const float4*)(vbase + (size_t)jn * DKK);
            const float4 nb = *(const float4*)(vbase + (size_t)jn * DKK + 4);
#pragma unroll
            for (int ti = 0; ti < TI; ti++) {
                const float e = s_s[ti * TIBLK + h * SROW + j];
                const float2 e2 = make_float2(e, e);
                acc[ti][0] = ffma2(e2, lo2(va), acc[ti][0]);
                acc[ti][1] = ffma2(e2, hi2(va), acc[ti][1]);
                acc[ti][2] = ffma2(e2, lo2(vb), acc[ti][2]);
                acc[ti][3] = ffma2(e2, hi2(vb), acc[ti][3]);
            }
            va = na; vb = nb;
        }
#pragma unroll
        for (int ti = 0; ti < TI; ti++)
#pragma unroll
            for (int c = 0; c < 4; c++) {
                acc[ti][c].x += __shfl_xor_sync(0xffffffffu, acc[ti][c].x, 8);
                acc[ti][c].x += __shfl_xor_sync(0xffffffffu, acc[ti][c].x, 16);
                acc[ti][c].y += __shfl_xor_sync(0xffffffffu, acc[ti][c].y, 8);
                acc[ti][c].y += __shfl_xor_sync(0xffffffffu, acc[ti][c].y, 16);
            }
        if (jj == 0) {
#pragma unroll
            for (int ti = 0; ti < TI; ti++) {
                float* rp = red1 + ((size_t)jh * TI * HH * DKK) +
                            (ti * HH + h) * DKK + dd * 8;
                *(float4*)rp       = make_float4(acc[ti][0].x, acc[ti][0].y,
                                                 acc[ti][1].x, acc[ti][1].y);
                *(float4*)(rp + 4) = make_float4(acc[ti][2].x, acc[ti][2].y,
                                                 acc[ti][3].x, acc[ti][3].y);
            }
        }
    };

    if ((bid & 1) == 0) { phase2b(); phase2a(); }
    else                { phase2a(); phase2b(); }
    __syncthreads();

    // ===== Combine + normalize + store (float4) =============================
    {
        const int Q = TI * HH * DKK / 4;            // 1024 float4s
        const float4* r14 = (const float4*)red1;
        const float4* r24 = (const float4*)red2;
#pragma unroll
        for (int it = 0; it < 2; it++) {
            const int idx4 = it * NT + tid;
            const float4 a0 = r14[idx4];
            const float4 a1 = r14[Q + idx4];
            const float4 c0 = r24[idx4];
            const float4 c1 = r24[Q + idx4];
            const int row = idx4 >> 4;               // ti*8+h
            const int ti  = row >> 3;
            const int h   = row & 7;
            const int d   = (idx4 & 15) << 2;
            const float s = 1.0f / (lpart[row] + lpart[TI * HH + row]);
            float4 o;
            o.x = ((a0.x + a1.x) + (c0.x + c1.x)) * s;
            o.y = ((a0.y + a1.y) + (c0.y + c1.y)) * s;
            o.z = ((a0.z + a1.z) + (c0.z + c1.z)) * s;
            o.w = ((a0.w + a1.w) + (c0.w + c1.w)) * s;
            *(float4*)&out[((size_t)(b * HH + h) * NN + (i0 + ti)) * DKK + d] = o;
        }
    }
}

extern "C" void kernel_launch(void* const* d_in, const int* in_sizes, int n_in,
                              void* d_out, int out_size) {
    const float* q    = (const float*)d_in[0];
    const float* k    = (const float*)d_in[1];
    const float* v    = (const float*)d_in[2];
    const float* rel  = (const float*)d_in[3];
    const float* mask = (const float*)d_in[4];
    float* out = (float*)d_out;

    cudaFuncSetAttribute(rel_attn_kernel,
                         cudaFuncAttributeMaxDynamicSharedMemorySize, SMEM_BYTES);
    rel_attn_kernel<<<BB * (NN / TI), NT, SMEM_BYTES>>>(q, k, v, rel, mask, out);
}

// round 17
// speedup vs baseline: 1.0950x; 1.0674x over previous
#include <cuda_runtime.h>
#include <cuda_bf16.h>
#include <math.h>

// Shapes fixed for this bench: B=4, H=8, N=512, DK=64
#define BB 4
#define HH 8
#define NN 512
#define DKK 64
#define TI 8                 // i-rows per CTA
#define NT 512               // threads per CTA (16 warps)
#define SCALE 0.125f         // 1/sqrt(64)
#define SROW 516             // padded score row (stride mod 32 = 4)
#define TIBLK (HH*SROW + 4)  // 4132 (stride mod 32 = 4)

// smem layout in floats
#define S_OFF    0
#define RED1_OFF (TI*TIBLK)                    // 33056 ; [2][TI*HH][DKK] p.v
#define RED2_OFF (RED1_OFF + 2*TI*HH*DKK)      // 41248 ; [2][TI*HH][DKK] p.rel
#define LP_OFF   (RED2_OFF + 2*TI*HH*DKK)      // 49440 ; [2][TI*HH] row sums
#define SMEM_FLOATS (LP_OFF + 2*TI*HH)         // 49568
#define SMEM_BYTES (SMEM_FLOATS * 4)           // 198272 (< 227 KB)

// ---------------- packed f32x2 helpers (FFMA2 on sm_103a) ----------------
__device__ __forceinline__ unsigned long long f2u(float2 a) {
    unsigned long long r;
    asm("mov.b64 %0, {%1, %2};" : "=l"(r) : "f"(a.x), "f"(a.y));
    return r;
}
__device__ __forceinline__ float2 u2f(unsigned long long a) {
    float2 r;
    asm("mov.b64 {%0, %1}, %2;" : "=f"(r.x), "=f"(r.y) : "l"(a));
    return r;
}
__device__ __forceinline__ float2 ffma2(float2 a, float2 b, float2 c) {
    unsigned long long r;
    asm("fma.rn.f32x2 %0, %1, %2, %3;"
        : "=l"(r) : "l"(f2u(a)), "l"(f2u(b)), "l"(f2u(c)));
    return u2f(r);
}
__device__ __forceinline__ float2 lo2(float4 v) { return make_float2(v.x, v.y); }
__device__ __forceinline__ float2 hi2(float4 v) { return make_float2(v.z, v.w); }

// Reduce 8 per-lane values r[0..7] across the 8 dd-lanes; lane dd -> sum of r[dd].
__device__ __forceinline__ float butterfly8(const float r[8],
                                            bool b0, bool b1, bool b2) {
    float c0 = b2 ? r[4] : r[0];
    float c1 = b2 ? r[5] : r[1];
    float c2 = b2 ? r[6] : r[2];
    float c3 = b2 ? r[7] : r[3];
    float d0 = b2 ? r[0] : r[4];
    float d1 = b2 ? r[1] : r[5];
    float d2 = b2 ? r[2] : r[6];
    float d3 = b2 ? r[3] : r[7];
    c0 += __shfl_xor_sync(0xffffffffu, d0, 4);
    c1 += __shfl_xor_sync(0xffffffffu, d1, 4);
    c2 += __shfl_xor_sync(0xffffffffu, d2, 4);
    c3 += __shfl_xor_sync(0xffffffffu, d3, 4);
    float e0 = b1 ? c2 : c0;
    float e1 = b1 ? c3 : c1;
    float f0 = b1 ? c0 : c2;
    float f1 = b1 ? c1 : c3;
    e0 += __shfl_xor_sync(0xffffffffu, f0, 2);
    e1 += __shfl_xor_sync(0xffffffffu, f1, 2);
    float w = b0 ? e1 : e0;
    float o = b0 ? e0 : e1;
    w += __shfl_xor_sync(0xffffffffu, o, 1);
    return w;
}

__global__ __launch_bounds__(NT, 1)
void rel_attn_kernel(const float* __restrict__ q,
                     const float* __restrict__ k,
                     const float* __restrict__ v,
                     const float* __restrict__ rel,
                     const float* __restrict__ mask,
                     float* __restrict__ out) {
    extern __shared__ float sm[];
    float* s_s   = sm + S_OFF;     // [TI]{[HH][SROW]} scores(+mask) -> e
    float* red1  = sm + RED1_OFF;  // [2][TI*HH][DKK] p.v per-jhalf partials
    float* red2  = sm + RED2_OFF;  // [2][TI*HH][DKK] p.rel per-jhalf partials
    float* lpart = sm + LP_OFF;    // [2][TI*HH] row-sum partials

    const int bid  = blockIdx.x;
    const int b    = bid >> 6;
    const int i0   = (bid & 63) * TI;
    const int tid  = threadIdx.x;
    const int warp = tid >> 5;
    const int lane = tid & 31;
    const int dd   = lane & 7;
    const int jj   = lane >> 3;
    const bool b0  = (dd & 1) != 0;
    const bool b1  = (dd & 2) != 0;
    const bool b2  = (dd & 4) != 0;

    const int sub  = warp & 7;           // head (1a/2a) or ti (1b/2b)
    const int jh   = warp >> 3;          // j-half owned by this warp
    const int jo   = jh * (NN / 2);

    const float2 z2 = make_float2(0.f, 0.f);

    // ===== Phase 1a: s = (scale*q).k + mask ; warp=(h, jhalf) ===============
    {
        const int h = sub;
        float4 qa[TI], qb[TI];
#pragma unroll
        for (int ti = 0; ti < TI; ti++) {
            const float* qp = q + ((size_t)(b * HH + h) * NN + (i0 + ti)) * DKK + dd * 8;
            float4 a = *(const float4*)qp;
            float4 c = *(const float4*)(qp + 4);
            a.x *= SCALE; a.y *= SCALE; a.z *= SCALE; a.w *= SCALE;
            c.x *= SCALE; c.y *= SCALE; c.z *= SCALE; c.w *= SCALE;
            qa[ti] = a; qb[ti] = c;
        }
        const float* kbase = k + ((size_t)(b * HH + h) * NN) * DKK + dd * 8;
        float4 ka = *(const float4*)(kbase + (size_t)(jo + jj) * DKK);
        float4 kb = *(const float4*)(kbase + (size_t)(jo + jj) * DKK + 4);
#pragma unroll 2
        for (int s = 0; s < NN / 8; s++) {
            const int j  = jo + s * 4 + jj;
            const int sn = (s < NN / 8 - 1) ? s + 1 : s;
            const int jn = jo + sn * 4 + jj;
            const float4 na = *(const float4*)(kbase + (size_t)jn * DKK);
            const float4 nb = *(const float4*)(kbase + (size_t)jn * DKK + 4);
            float r[TI];
#pragma unroll
            for (int ti = 0; ti < TI; ti++) {
                float2 a = ffma2(lo2(qa[ti]), lo2(ka), z2);
                a = ffma2(hi2(qa[ti]), hi2(ka), a);
                a = ffma2(lo2(qb[ti]), lo2(kb), a);
                a = ffma2(hi2(qb[ti]), hi2(kb), a);
                r[ti] = a.x + a.y;
            }
            const float w = butterfly8(r, b0, b1, b2);   // lane dd -> ti=dd
            s_s[dd * TIBLK + h * SROW + j] = w;          // conflict-free
            ka = na; kb = nb;
        }

        // --- mask epilogue: s_s rows (all ti, h, j in jhalf) += mask --------
#pragma unroll
        for (int ti = 0; ti < TI; ti++) {
            const float4* mp4 = (const float4*)(mask +
                ((size_t)(b * HH + h) * NN + (i0 + ti)) * NN + jo);
            float4* sr4 = (float4*)(s_s + ti * TIBLK + h * SROW + jo);
#pragma unroll
            for (int t = 0; t < 2; t++) {
                const int x = t * 32 + lane;             // 64 float4 per row-half
                float4 sv = sr4[x];
                const float4 mv = mp4[x];
                sv.x += mv.x; sv.y += mv.y; sv.z += mv.z; sv.w += mv.w;
                sr4[x] = sv;
            }
        }
    }
    __syncthreads();

    // ===== Phase 1b: e = exp(q.rel + s_s) ; warp=(ti, jhalf) ================
    {
        const int ti = sub;
        float4 qa[HH], qb[HH];
#pragma unroll
        for (int h = 0; h < HH; h++) {
            const float* qp = q + ((size_t)(b * HH + h) * NN + (i0 + ti)) * DKK + dd * 8;
            qa[h] = *(const float4*)qp;
            qb[h] = *(const float4*)(qp + 4);
        }
        const float* rbase = rel + (((size_t)b * NN + (i0 + ti)) * NN) * DKK + dd * 8;
        float* srow = s_s + ti * TIBLK + dd * SROW;
        float lsum = 0.f;

        float4 ra = __ldg((const float4*)(rbase + (size_t)(jo + jj) * DKK));
        float4 rb = __ldg((const float4*)(rbase + (size_t)(jo + jj) * DKK + 4));
#pragma unroll 2
        for (int s = 0; s < NN / 8; s++) {
            const int j  = jo + s * 4 + jj;
            const int sn = (s < NN / 8 - 1) ? s + 1 : s;
            const int jn = jo + sn * 4 + jj;
            const float4 na = __ldg((const float4*)(rbase + (size_t)jn * DKK));
            const float4 nb = __ldg((const float4*)(rbase + (size_t)jn * DKK + 4));
            float r[HH];
#pragma unroll
            for (int h = 0; h < HH; h++) {
                float2 a = ffma2(lo2(qa[h]), lo2(ra), z2);
                a = ffma2(hi2(qa[h]), hi2(ra), a);
                a = ffma2(lo2(qb[h]), lo2(rb), a);
                a = ffma2(hi2(qb[h]), hi2(rb), a);
                r[h] = a.x + a.y;
            }
            const float w = butterfly8(r, b0, b1, b2);   // lane dd -> h=dd
            const float e = __expf(w + srow[j]);         // content+mask in s_s
            srow[j] = e;                                 // conflict-free RMW
            lsum += e;
            ra = na; rb = nb;
        }
        // row-sum partial: reduce over the 4 jj lanes for fixed dd
        lsum += __shfl_xor_sync(0xffffffffu, lsum, 8);
        lsum += __shfl_xor_sync(0xffffffffu, lsum, 16);
        if (jj == 0) lpart[jh * (TI * HH) + ti * HH + dd] = lsum;
    }
    __syncthreads();

    // ===== Phases 2a / 2b (order alternates by CTA parity) ==================
    // New j partition inside each phase: jj-group owns j = jo + 8*jj + 32*m + 4*u
    // (bank offsets 8*jj -> {0,8,16,24}: conflict-free float4 e-loads).

    auto phase2b = [&]() {   // out2 = p.rel ; warp=(ti, jhalf), m DESCENDING
        const int ti = sub;
        float2 acc[HH][4];
#pragma unroll
        for (int h = 0; h < HH; h++)
#pragma unroll
            for (int c = 0; c < 4; c++) acc[h][c] = z2;

        const float* rbase = rel + (((size_t)b * NN + (i0 + ti)) * NN) * DKK + dd * 8;
        const float* sb = s_s + ti * TIBLK;
#pragma unroll 2
        for (int mu = 15; mu >= 0; mu--) {
            const int j0 = jo + 8 * jj + 32 * (mu >> 1) + 4 * (mu & 1);
            const float* rp = rbase + (size_t)j0 * DKK;
            const float4 r0a = __ldcs((const float4*)(rp));
            const float4 r0b = __ldcs((const float4*)(rp + 4));
            const float4 r1a = __ldcs((const float4*)(rp + DKK));
            const float4 r1b = __ldcs((const float4*)(rp + DKK + 4));
            const float4 r2a = __ldcs((const float4*)(rp + 2 * DKK));
            const float4 r2b = __ldcs((const float4*)(rp + 2 * DKK + 4));
            const float4 r3a = __ldcs((const float4*)(rp + 3 * DKK));
            const float4 r3b = __ldcs((const float4*)(rp + 3 * DKK + 4));
#pragma unroll
            for (int h = 0; h < HH; h++) {
                const float4 e4 = *(const float4*)(sb + h * SROW + j0);
                const float2 p0 = make_float2(e4.x, e4.x);
                const float2 p1 = make_float2(e4.y, e4.y);
                const float2 p2 = make_float2(e4.z, e4.z);
                const float2 p3 = make_float2(e4.w, e4.w);
                acc[h][0] = ffma2(p0, lo2(r0a), acc[h][0]);
                acc[h][1] = ffma2(p0, hi2(r0a), acc[h][1]);
                acc[h][2] = ffma2(p0, lo2(r0b), acc[h][2]);
                acc[h][3] = ffma2(p0, hi2(r0b), acc[h][3]);
                acc[h][0] = ffma2(p1, lo2(r1a), acc[h][0]);
                acc[h][1] = ffma2(p1, hi2(r1a), acc[h][1]);
                acc[h][2] = ffma2(p1, lo2(r1b), acc[h][2]);
                acc[h][3] = ffma2(p1, hi2(r1b), acc[h][3]);
                acc[h][0] = ffma2(p2, lo2(r2a), acc[h][0]);
                acc[h][1] = ffma2(p2, hi2(r2a), acc[h][1]);
                acc[h][2] = ffma2(p2, lo2(r2b), acc[h][2]);
                acc[h][3] = ffma2(p2, hi2(r2b), acc[h][3]);
                acc[h][0] = ffma2(p3, lo2(r3a), acc[h][0]);
                acc[h][1] = ffma2(p3, hi2(r3a), acc[h][1]);
                acc[h][2] = ffma2(p3, lo2(r3b), acc[h][2]);
                acc[h][3] = ffma2(p3, hi2(r3b), acc[h][3]);
            }
        }
#pragma unroll
        for (int h = 0; h < HH; h++)
#pragma unroll
            for (int c = 0; c < 4; c++) {
                acc[h][c].x += __shfl_xor_sync(0xffffffffu, acc[h][c].x, 8);
                acc[h][c].x += __shfl_xor_sync(0xffffffffu, acc[h][c].x, 16);
                acc[h][c].y += __shfl_xor_sync(0xffffffffu, acc[h][c].y, 8);
                acc[h][c].y += __shfl_xor_sync(0xffffffffu, acc[h][c].y, 16);
            }
        if (jj == 0) {
#pragma unroll
            for (int h = 0; h < HH; h++) {
                float* rp = red2 + ((size_t)jh * TI * HH * DKK) +
                            (ti * HH + h) * DKK + dd * 8;
                *(float4*)rp       = make_float4(acc[h][0].x, acc[h][0].y,
                                                 acc[h][1].x, acc[h][1].y);
                *(float4*)(rp + 4) = make_float4(acc[h][2].x, acc[h][2].y,
                                                 acc[h][3].x, acc[h][3].y);
            }
        }
    };

    auto phase2a = [&]() {   // out1 = p.v ; warp=(h, jhalf)
        const int h = sub;
        float2 acc[TI][4];
#pragma unroll
        for (int ti = 0; ti < TI; ti++)
#pragma unroll
            for (int c = 0; c < 4; c++) acc[ti][c] = z2;

        const float* vbase = v + ((size_t)(b * HH + h) * NN) * DKK + dd * 8;
        const float* sb = s_s + h * SROW;
#pragma unroll 2
        for (int mu = 0; mu < 16; mu++) {
            const int j0 = jo + 8 * jj + 32 * (mu >> 1) + 4 * (mu & 1);
            const float* vp = vbase + (size_t)j0 * DKK;
            const float4 v0a = *(const float4*)(vp);
            const float4 v0b = *(const float4*)(vp + 4);
            const float4 v1a = *(const float4*)(vp + DKK);
            const float4 v1b = *(const float4*)(vp + DKK + 4);
            const float4 v2a = *(const float4*)(vp + 2 * DKK);
            const float4 v2b = *(const float4*)(vp + 2 * DKK + 4);
            const float4 v3a = *(const float4*)(vp + 3 * DKK);
            const float4 v3b = *(const float4*)(vp + 3 * DKK + 4);
#pragma unroll
            for (int ti = 0; ti < TI; ti++) {
                const float4 e4 = *(const float4*)(sb + ti * TIBLK + j0);
                const float2 p0 = make_float2(e4.x, e4.x);
                const float2 p1 = make_float2(e4.y, e4.y);
                const float2 p2 = make_float2(e4.z, e4.z);
                const float2 p3 = make_float2(e4.w, e4.w);
                acc[ti][0] = ffma2(p0, lo2(v0a), acc[ti][0]);
                acc[ti][1] = ffma2(p0, hi2(v0a), acc[ti][1]);
                acc[ti][2] = ffma2(p0, lo2(v0b), acc[ti][2]);
                acc[ti][3] = ffma2(p0, hi2(v0b), acc[ti][3]);
                acc[ti][0] = ffma2(p1, lo2(v1a), acc[ti][0]);
                acc[ti][1] = ffma2(p1, hi2(v1a), acc[ti][1]);
                acc[ti][2] = ffma2(p1, lo2(v1b), acc[ti][2]);
                acc[ti][3] = ffma2(p1, hi2(v1b), acc[ti][3]);
                acc[ti][0] = ffma2(p2, lo2(v2a), acc[ti][0]);
                acc[ti][1] = ffma2(p2, hi2(v2a), acc[ti][1]);
                acc[ti][2] = ffma2(p2, lo2(v2b), acc[ti][2]);
                acc[ti][3] = ffma2(p2, hi2(v2b), acc[ti][3]);
                acc[ti][0] = ffma2(p3, lo2(v3a), acc[ti][0]);
                acc[ti][1] = ffma2(p3, hi2(v3a), acc[ti][1]);
                acc[ti][2] = ffma2(p3, lo2(v3b), acc[ti][2]);
                acc[ti][3] = ffma2(p3, hi2(v3b), acc[ti][3]);
            }
        }
#pragma unroll
        for (int ti = 0; ti < TI; ti++)
#pragma unroll
            for (int c = 0; c < 4; c++) {
                acc[ti][c].x += __shfl_xor_sync(0xffffffffu, acc[ti][c].x, 8);
                acc[ti][c].x += __shfl_xor_sync(0xffffffffu, acc[ti][c].x, 16);
                acc[ti][c].y += __shfl_xor_sync(0xffffffffu, acc[ti][c].y, 8);
                acc[ti][c].y += __shfl_xor_sync(0xffffffffu, acc[ti][c].y, 16);
            }
        if (jj == 0) {
#pragma unroll
            for (int ti = 0; ti < TI; ti++) {
                float* rp = red1 + ((size_t)jh * TI * HH * DKK) +
                            (ti * HH + h) * DKK + dd * 8;
                *(float4*)rp       = make_float4(acc[ti][0].x, acc[ti][0].y,
                                                 acc[ti][1].x, acc[ti][1].y);
                *(float4*)(rp + 4) = make_float4(acc[ti][2].x, acc[ti][2].y,
                                                 acc[ti][3].x, acc[ti][3].y);
            }
        }
    };

    if ((bid & 1) == 0) { phase2b(); phase2a(); }
    else                { phase2a(); phase2b(); }
    __syncthreads();

    // ===== Combine + normalize + store (float4) =============================
    {
        const int Q = TI * HH * DKK / 4;            // 1024 float4s
        const float4* r14 = (const float4*)red1;
        const float4* r24 = (const float4*)red2;
#pragma unroll
        for (int it = 0; it < 2; it++) {
            const int idx4 = it * NT + tid;
            const float4 a0 = r14[idx4];
            const float4 a1 = r14[Q + idx4];
            const float4 c0 = r24[idx4];
            const float4 c1 = r24[Q + idx4];
            const int row = idx4 >> 4;               // ti*8+h
            const int ti  = row >> 3;
            const int h   = row & 7;
            const int d   = (idx4 & 15) << 2;
            const float s = 1.0f / (lpart[row] + lpart[TI * HH + row]);
            float4 o;
            o.x = ((a0.x + a1.x) + (c0.x + c1.x)) * s;
            o.y = ((a0.y + a1.y) + (c0.y + c1.y)) * s;
            o.z = ((a0.z + a1.z) + (c0.z + c1.z)) * s;
            o.w = ((a0.w + a1.w) + (c0.w + c1.w)) * s;
            *(float4*)&out[((size_t)(b * HH + h) * NN + (i0 + ti)) * DKK + d] = o;
        }
    }
}

extern "C" void kernel_launch(void* const* d_in, const int* in_sizes, int n_in,
                              void* d_out, int out_size) {
    const float* q    = (const float*)d_in[0];
    const float* k    = (const float*)d_in[1];
    const float* v    = (const float*)d_in[2];
    const float* rel  = (const float*)d_in[3];
    const float* mask = (const float*)d_in[4];
    float* out = (float*)d_out;

    cudaFuncSetAttribute(rel_attn_kernel,
                         cudaFuncAttributeMaxDynamicSharedMemorySize, SMEM_BYTES);
    rel_attn_kernel<<<BB * (NN / TI), NT, SMEM_BYTES>>>(q, k, v, rel, mask, out);
}